// round 16
// baseline (speedup 1.0000x reference)
#include <cuda_runtime.h>
#include <cstdint>

#define N_MAX  100000
#define E_MAXC 3200000
#define E_PAD  (E_MAXC + 8 * N_MAX + 8)   // padded CSR + 8 slack for idx prefetch overread
#define IN_F   512
#define HID    16
#define NCLS   7

typedef unsigned long long ull;

// ---- scratch (no allocations allowed) ----
__device__ int    s_cnt[N_MAX];            // true in-degree (excl. self-loop)
__device__ int    s_row[N_MAX];            // CSR row start (padded layout)
__device__ int    s_cur[N_MAX];            // fill cursor
__device__ int    s_bsum[512];             // per-block totals from scanA
__device__ float  s_dinv[N_MAX];
__device__ float4 s_g1[(N_MAX + 1) * 4];   // [N+1][16]; row N = zeros (sentinel)
__device__ float4 s_g2[(N_MAX + 1) * 2];   // [N+1][8];  row N = zeros (sentinel)
__device__ int    s_csr[E_PAD];            // src indices grouped by dst, pad = n

// ---- f32x2 packed math (sm_100+) ----
#define FMA2(d, a, b, c) asm("fma.rn.f32x2 %0, %1, %2, %3;" : "=l"(d) : "l"(a), "l"(b), "l"(c))
#define ADD2(d, a, b)    asm("add.rn.f32x2 %0, %1, %2;"     : "=l"(d) : "l"(a), "l"(b))
#define MUL2(d, a, b)    asm("mul.rn.f32x2 %0, %1, %2;"     : "=l"(d) : "l"(a), "l"(b))
#define PACK2(d, s)      asm("mov.b64 %0, {%1, %1};"        : "=l"(d) : "r"(__float_as_uint(s)))
#define PACKAB(d, lo, hi) asm("mov.b64 %0, {%1, %2};"       : "=l"(d) : "f"(lo), "f"(hi))

__device__ __forceinline__ float lo32(ull p) { return __uint_as_float((unsigned)p); }
__device__ __forceinline__ float hi32(ull p) { return __uint_as_float((unsigned)(p >> 32)); }

// ================= build =================
__global__ void k_zero(int n, int csr4) {
    int i = blockIdx.x * blockDim.x + threadIdx.x;
    if (i < n) s_cnt[i] = 0;
    if (i < csr4) ((int4*)s_csr)[i] = make_int4(n, n, n, n);
    if (i < 4) s_g1[(size_t)n * 4 + i] = make_float4(0.f, 0.f, 0.f, 0.f);
    if (i < 2) s_g2[(size_t)n * 2 + i] = make_float4(0.f, 0.f, 0.f, 0.f);
}

__global__ void k_hist(const int* __restrict__ dst, int e) {
    int i = blockIdx.x * blockDim.x + threadIdx.x;
    if (i < e) atomicAdd(&s_cnt[dst[i]], 1);
}

__global__ void k_scanA(int n) {
    __shared__ int sh[256];
    const int t = threadIdx.x;
    const int i = blockIdx.x * 256 + t;
    int c = (i < n) ? s_cnt[i] : 0;
    int v = (c + 7) & ~7;
    sh[t] = v;
    __syncthreads();
    #pragma unroll
    for (int off = 1; off < 256; off <<= 1) {
        int add = (t >= off) ? sh[t - off] : 0;
        __syncthreads();
        sh[t] += add;
        __syncthreads();
    }
    if (i < n) {
        s_row[i]  = sh[t] - v;
        s_dinv[i] = rsqrtf((float)(c + 1));
    }
    if (t == 255) s_bsum[blockIdx.x] = sh[255];
}

__global__ void k_scanC(int n) {
    __shared__ int red[256];
    const int t = threadIdx.x;
    const int b = blockIdx.x;
    int p = 0;
    for (int j = t; j < b; j += 256) p += s_bsum[j];
    red[t] = p;
    __syncthreads();
    #pragma unroll
    for (int off = 128; off >= 1; off >>= 1) {
        if (t < off) red[t] += red[t + off];
        __syncthreads();
    }
    const int base = red[0];
    const int i = b * 256 + t;
    if (i >= n) return;
    int st = s_row[i] + base;
    s_row[i] = st;
    s_cur[i] = st;
}

__global__ void k_fill(const int* __restrict__ src, const int* __restrict__ dst, int e) {
    int i = blockIdx.x * blockDim.x + threadIdx.x;
    if (i >= e) return;
    int p = atomicAdd(&s_cur[dst[i]], 1);
    s_csr[p] = src[i];
}

// ================= layer-1 GEMM: g1[i] = dinv[i] * (x[i] @ W1) =================
// BARRIER-FREE main loop. Thread-per-row; X read straight from global into a
// register double-buffer: chunk = K=32 = one full 128B line per row (line
// fetched once, fully consumed => DRAM-optimal), prefetched one chunk ahead
// (~512 issue-cyc > DRAM latency). W (32KB) smem-resident, warp-uniform
// LDS.128 broadcasts; ONE __syncthreads in the whole kernel. Two statically
// named buffers + manually 2-unrolled chunk loop => no spills. The R10-R15
// profiles proved the staged-X pipeline was convoy-bound (3100 cyc/tile vs
// 450 cyc of work, invariant to L1 traffic halving); this removes the convoy.
#define G1_ROWS 256

__global__ void __launch_bounds__(256, 2) k_gemm1(const float* __restrict__ x,
                                                  const float* __restrict__ W1, int n) {
    __shared__ float Ws[IN_F * HID];    // 32 KB (only smem)

    const int t = threadIdx.x;
    #pragma unroll
    for (int i = 0; i < 8; i++)
        ((float4*)Ws)[i * 256 + t] = ((const float4*)W1)[i * 256 + t];
    __syncthreads();

    const int row = blockIdx.x * G1_ROWS + t;
    const int srow = (row < n) ? row : (n - 1);           // clamp: safe reads, result discarded
    const float4* xr = (const float4*)(x + (size_t)srow * IN_F);   // 128 float4

    ull acc[8] = {0, 0, 0, 0, 0, 0, 0, 0};
    float4 buf0[8], buf1[8];

    #pragma unroll
    for (int j = 0; j < 8; j++) buf0[j] = __ldg(xr + j);  // chunk 0

#define G1_COMPUTE(BUF, CBASE)                                                     \
    {                                                                              \
        _Pragma("unroll")                                                          \
        for (int q = 0; q < 8; q++) {                                              \
            float4 xv = BUF[q];                                                    \
            _Pragma("unroll")                                                      \
            for (int jj = 0; jj < 4; jj++) {                                       \
                ull xx;                                                            \
                PACK2(xx, ((const float*)&xv)[jj]);                                \
                const ulonglong2* wr =                                             \
                    (const ulonglong2*)(Ws + ((CBASE) * 32 + q * 4 + jj) * HID);   \
                ulonglong2 wa = wr[0], wb = wr[1], wc = wr[2], wd = wr[3];         \
                FMA2(acc[0], xx, wa.x, acc[0]); FMA2(acc[1], xx, wa.y, acc[1]);    \
                FMA2(acc[2], xx, wb.x, acc[2]); FMA2(acc[3], xx, wb.y, acc[3]);    \
                FMA2(acc[4], xx, wc.x, acc[4]); FMA2(acc[5], xx, wc.y, acc[5]);    \
                FMA2(acc[6], xx, wd.x, acc[6]); FMA2(acc[7], xx, wd.y, acc[7]);    \
            }                                                                      \
        }                                                                          \
    }

    #pragma unroll 1
    for (int c = 0; c < 16; c += 2) {
        #pragma unroll
        for (int j = 0; j < 8; j++) buf1[j] = __ldg(xr + (c + 1) * 8 + j);  // prefetch c+1
        G1_COMPUTE(buf0, c);
        if (c + 2 < 16) {
            #pragma unroll
            for (int j = 0; j < 8; j++) buf0[j] = __ldg(xr + (c + 2) * 8 + j);  // prefetch c+2
        }
        G1_COMPUTE(buf1, c + 1);
    }
#undef G1_COMPUTE

    if (row >= n) return;

    const float di = s_dinv[row];
    ull dd;
    PACK2(dd, di);
    #pragma unroll
    for (int jj = 0; jj < 8; jj++) MUL2(acc[jj], acc[jj], dd);

    #pragma unroll
    for (int m = 0; m < 4; m++) {
        float4 v;
        v.x = lo32(acc[2 * m]);     v.y = hi32(acc[2 * m]);
        v.z = lo32(acc[2 * m + 1]); v.w = hi32(acc[2 * m + 1]);
        s_g1[(size_t)row * 4 + m] = v;
    }
}

// ================= layer-1 gather + fused mid =================
__global__ void __launch_bounds__(256) k_gather1(const float* __restrict__ b1,
                                                 const float* __restrict__ W2, int n) {
    __shared__ float W2s[HID * NCLS];
    __shared__ float b1s[HID];
    const int t = threadIdx.x;
    if (t < HID * NCLS) W2s[t] = W2[t];
    if (t < HID)        b1s[t] = b1[t];
    __syncthreads();

    const int g = (blockIdx.x * 256 + t) >> 2;
    const int m = t & 3;
    if (g >= n) return;

    const ulonglong2* G1 = (const ulonglong2*)s_g1;
    ulonglong2 acc = G1[(size_t)g * 4 + m];     // self-loop term
    const int cnt  = s_cnt[g];
    const int pcnt = (cnt + 7) & ~7;
    const int* cp  = s_csr + s_row[g];

    int ii[8];
    #pragma unroll
    for (int j = 0; j < 8; j++) ii[j] = __ldg(cp + j);

    for (int it = 0; it < pcnt; it += 8) {
        ulonglong2 v[8];
        #pragma unroll
        for (int j = 0; j < 8; j++) v[j] = __ldg(&G1[(size_t)ii[j] * 4 + m]);
        #pragma unroll
        for (int j = 0; j < 8; j++) ii[j] = __ldg(cp + it + 8 + j);  // prefetch
        #pragma unroll
        for (int j = 0; j < 8; j++) {
            ADD2(acc.x, acc.x, v[j].x);
            ADD2(acc.y, acc.y, v[j].y);
        }
    }

    const float di = s_dinv[g];
    float h[4];
    h[0] = fmaxf(fmaf(di, lo32(acc.x), b1s[m * 4 + 0]), 0.f);
    h[1] = fmaxf(fmaf(di, hi32(acc.x), b1s[m * 4 + 1]), 0.f);
    h[2] = fmaxf(fmaf(di, lo32(acc.y), b1s[m * 4 + 2]), 0.f);
    h[3] = fmaxf(fmaf(di, hi32(acc.y), b1s[m * 4 + 3]), 0.f);

    float u[8] = {0.f, 0.f, 0.f, 0.f, 0.f, 0.f, 0.f, 0.f};
    #pragma unroll
    for (int jj = 0; jj < 4; jj++) {
        const int j = m * 4 + jj;
        #pragma unroll
        for (int c = 0; c < NCLS; c++)
            u[c] = fmaf(h[jj], W2s[j * NCLS + c], u[c]);
    }

    ull p[4];
    PACKAB(p[0], u[0], u[1]);
    PACKAB(p[1], u[2], u[3]);
    PACKAB(p[2], u[4], u[5]);
    PACKAB(p[3], u[6], u[7]);
    #pragma unroll
    for (int off = 1; off <= 2; off <<= 1) {
        #pragma unroll
        for (int q = 0; q < 4; q++) {
            ull o = __shfl_xor_sync(0xffffffffu, p[q], off);
            ADD2(p[q], p[q], o);
        }
    }
    ull dd;
    PACK2(dd, di);
    #pragma unroll
    for (int q = 0; q < 4; q++) MUL2(p[q], p[q], dd);

    if (m == 0) {
        float4 v = make_float4(lo32(p[0]), hi32(p[0]), lo32(p[1]), hi32(p[1]));
        s_g2[(size_t)g * 2 + 0] = v;
    } else if (m == 1) {
        float4 v = make_float4(lo32(p[2]), hi32(p[2]), lo32(p[3]), hi32(p[3]));
        s_g2[(size_t)g * 2 + 1] = v;
    }
}

// ================= layer-2 gather + fused final output =================
__global__ void __launch_bounds__(256) k_gather2(const float* __restrict__ b2,
                                                 float* __restrict__ out, int n) {
    const int t = threadIdx.x;
    const int g = (blockIdx.x * 256 + t) >> 2;
    const int m = t & 3;
    if (g >= n) return;

    const ull* G2 = (const ull*)s_g2;
    ull acc = G2[(size_t)g * 4 + m];            // self-loop term
    const int cnt  = s_cnt[g];
    const int pcnt = (cnt + 7) & ~7;
    const int* cp  = s_csr + s_row[g];

    int ii[8];
    #pragma unroll
    for (int j = 0; j < 8; j++) ii[j] = __ldg(cp + j);

    for (int it = 0; it < pcnt; it += 8) {
        ull v[8];
        #pragma unroll
        for (int j = 0; j < 8; j++) v[j] = __ldg(&G2[(size_t)ii[j] * 4 + m]);
        #pragma unroll
        for (int j = 0; j < 8; j++) ii[j] = __ldg(cp + it + 8 + j);  // prefetch
        #pragma unroll
        for (int j = 0; j < 8; j++) ADD2(acc, acc, v[j]);
    }

    const float di = s_dinv[g];
    const int c0 = m * 2;
    float* orow = out + (size_t)g * NCLS;
    orow[c0] = fmaf(di, lo32(acc), __ldg(b2 + c0));
    if (c0 + 1 < NCLS)
        orow[c0 + 1] = fmaf(di, hi32(acc), __ldg(b2 + c0 + 1));
}

extern "C" void kernel_launch(void* const* d_in, const int* in_sizes, int n_in,
                              void* d_out, int out_size) {
    const float* x  = (const float*)d_in[0];
    const int*   ei = (const int*)  d_in[1];
    const float* W1 = (const float*)d_in[2];
    const float* b1 = (const float*)d_in[3];
    const float* W2 = (const float*)d_in[4];
    const float* b2 = (const float*)d_in[5];
    float* out = (float*)d_out;

    const int n = in_sizes[0] / IN_F;     // 100000
    const int e = in_sizes[1] / 2;        // 3200000
    const int* src = ei;
    const int* dst = ei + e;

    const int csr_len = e + 8 * n;
    const int csr4    = (csr_len + 3) / 4;

    const int nb = (n + 255) / 256;
    const int eb = (e + 255) / 256;
    const int zb = (csr4 > n ? csr4 + 255 : n + 255) / 256;
    const int gb = (n + G1_ROWS - 1) / G1_ROWS;   // 391 blocks
    const int g4 = (4 * n + 255) / 256;

    // gemm1 stays at launch index 3 (the ncu-profiled slot).
    k_zero   <<<zb, 256>>>(n, csr4);
    k_hist   <<<eb, 256>>>(dst, e);
    k_scanA  <<<nb, 256>>>(n);
    k_gemm1  <<<gb, 256>>>(x, W1, n);
    k_scanC  <<<nb, 256>>>(n);
    k_fill   <<<eb, 256>>>(src, dst, e);
    k_gather1<<<g4, 256>>>(b1, W2, n);
    k_gather2<<<g4, 256>>>(b2, out, n);
}

// round 17
// speedup vs baseline: 1.2036x; 1.2036x over previous
#include <cuda_runtime.h>
#include <cstdint>

#define N_MAX  100000
#define E_MAXC 3200000
#define E_PAD  (E_MAXC + 8 * N_MAX + 8)   // padded CSR + 8 slack for idx prefetch overread
#define IN_F   512
#define HID    16
#define NCLS   7

typedef unsigned long long ull;

// ---- scratch (no allocations allowed) ----
__device__ int    s_cnt[N_MAX];            // true in-degree (excl. self-loop)
__device__ int    s_row[N_MAX];            // CSR row start (padded layout)
__device__ int    s_cur[N_MAX];            // fill cursor
__device__ int    s_bsum[512];             // per-block totals from scanA
__device__ float  s_dinv[N_MAX];
__device__ float4 s_g1[(N_MAX + 1) * 4];   // [N+1][16]; row N = zeros (sentinel)
__device__ float4 s_g2[(N_MAX + 1) * 2];   // [N+1][8];  row N = zeros (sentinel)
__device__ int    s_csr[E_PAD];            // src indices grouped by dst, pad = n

// ---- f32x2 packed math (sm_100+) ----
#define FMA2(d, a, b, c) asm("fma.rn.f32x2 %0, %1, %2, %3;" : "=l"(d) : "l"(a), "l"(b), "l"(c))
#define ADD2(d, a, b)    asm("add.rn.f32x2 %0, %1, %2;"     : "=l"(d) : "l"(a), "l"(b))
#define MUL2(d, a, b)    asm("mul.rn.f32x2 %0, %1, %2;"     : "=l"(d) : "l"(a), "l"(b))
#define PACK2(d, s)      asm("mov.b64 %0, {%1, %1};"        : "=l"(d) : "r"(__float_as_uint(s)))
#define PACKAB(d, lo, hi) asm("mov.b64 %0, {%1, %2};"       : "=l"(d) : "f"(lo), "f"(hi))

__device__ __forceinline__ float lo32(ull p) { return __uint_as_float((unsigned)p); }
__device__ __forceinline__ float hi32(ull p) { return __uint_as_float((unsigned)(p >> 32)); }

// ================= build =================
__global__ void k_zero(int n, int csr4) {
    int i = blockIdx.x * blockDim.x + threadIdx.x;
    if (i < n) s_cnt[i] = 0;
    if (i < csr4) ((int4*)s_csr)[i] = make_int4(n, n, n, n);
    if (i < 4) s_g1[(size_t)n * 4 + i] = make_float4(0.f, 0.f, 0.f, 0.f);
    if (i < 2) s_g2[(size_t)n * 2 + i] = make_float4(0.f, 0.f, 0.f, 0.f);
}

__global__ void k_hist(const int* __restrict__ dst, int e) {
    int i = blockIdx.x * blockDim.x + threadIdx.x;
    if (i < e) atomicAdd(&s_cnt[dst[i]], 1);
}

__global__ void k_scanA(int n) {
    __shared__ int sh[256];
    const int t = threadIdx.x;
    const int i = blockIdx.x * 256 + t;
    int c = (i < n) ? s_cnt[i] : 0;
    int v = (c + 7) & ~7;
    sh[t] = v;
    __syncthreads();
    #pragma unroll
    for (int off = 1; off < 256; off <<= 1) {
        int add = (t >= off) ? sh[t - off] : 0;
        __syncthreads();
        sh[t] += add;
        __syncthreads();
    }
    if (i < n) {
        s_row[i]  = sh[t] - v;
        s_dinv[i] = rsqrtf((float)(c + 1));
    }
    if (t == 255) s_bsum[blockIdx.x] = sh[255];
}

__global__ void k_scanC(int n) {
    __shared__ int red[256];
    const int t = threadIdx.x;
    const int b = blockIdx.x;
    int p = 0;
    for (int j = t; j < b; j += 256) p += s_bsum[j];
    red[t] = p;
    __syncthreads();
    #pragma unroll
    for (int off = 128; off >= 1; off >>= 1) {
        if (t < off) red[t] += red[t + off];
        __syncthreads();
    }
    const int base = red[0];
    const int i = b * 256 + t;
    if (i >= n) return;
    int st = s_row[i] + base;
    s_row[i] = st;
    s_cur[i] = st;
}

__global__ void k_fill(const int* __restrict__ src, const int* __restrict__ dst, int e) {
    int i = blockIdx.x * blockDim.x + threadIdx.x;
    if (i >= e) return;
    int p = atomicAdd(&s_cur[dst[i]], 1);
    s_csr[p] = src[i];
}

// ================= layer-1 GEMM: g1[i] = dinv[i] * (x[i] @ W1) =================
// SPLIT-K x4: every design at <=100K threads plateaued at ~110us (latency-
// limited at 15-26% occ regardless of traffic). Here 4 lanes per row-pair
// (rowA = base+P, rowB = rowA+64), lane s covers k with (k>>2)&3 == s
// (16B-interleaved slices: X lines stay fully consumed, 8 lines/warp-instr).
// 200K threads. W traffic unchanged (same row-group x k instances). W stored
// swizzled: logical 16B slot q of row k at physical q ^ ((k>>2)&3), so the 4
// s-lanes of a group hit 4 distinct bank-spans (s*256B = 0 mod 32 words;
// separation is (q^s)*4 words) while 8 row-groups broadcast => conflict-free.
// (k>>2)&3 == s is per-thread constant => pure address math, accs stay in
// logical order. Final: 2-step butterfly shfl in the 4-lane group (uniform
// trip count => full-mask safe), lane 0 scales by dinv and writes both rows.
#define G1_ROWS 128

__global__ void __launch_bounds__(256) k_gemm1(const float* __restrict__ x,
                                               const float* __restrict__ W1, int n) {
    __shared__ float Ws[IN_F * HID];    // 32 KB, slot-swizzled
    const int t = threadIdx.x;

    #pragma unroll
    for (int i0 = 0; i0 < 8; i0++) {
        int i = i0 * 256 + t;           // float4 index 0..2047
        int k = i >> 2, q = i & 3;
        int qp = q ^ ((k >> 2) & 3);
        ((float4*)Ws)[k * 4 + qp] = ((const float4*)W1)[i];
    }
    __syncthreads();

    const int P = t >> 2;               // 0..63: row-pair within block
    const int s = t & 3;                // k-splitter
    const int rowA = blockIdx.x * G1_ROWS + P;
    const int rowB = rowA + 64;
    const int srA = (rowA < n) ? rowA : (n - 1);   // clamped reads, guarded writes
    const int srB = (rowB < n) ? rowB : (n - 1);
    const float4* xA = (const float4*)(x + (size_t)srA * IN_F);
    const float4* xB = (const float4*)(x + (size_t)srB * IN_F);

    ull accA[8] = {0, 0, 0, 0, 0, 0, 0, 0};
    ull accB[8] = {0, 0, 0, 0, 0, 0, 0, 0};

    const int o0 = (0 ^ s) << 2, o1 = (1 ^ s) << 2;   // physical slot float-offsets
    const int o2 = (2 ^ s) << 2, o3 = (3 ^ s) << 2;

#define G1_COMP(VA, VB, CC)                                                        \
    {                                                                              \
        _Pragma("unroll")                                                          \
        for (int j = 0; j < 4; j++) {                                              \
            ull xa, xb;                                                            \
            PACK2(xa, ((const float*)&(VA))[j]);                                   \
            PACK2(xb, ((const float*)&(VB))[j]);                                   \
            const float* wk = Ws + ((4 * (CC) + s) * 4 + j) * HID;                 \
            ulonglong2 w0 = *(const ulonglong2*)(wk + o0);                         \
            ulonglong2 w1 = *(const ulonglong2*)(wk + o1);                         \
            ulonglong2 w2 = *(const ulonglong2*)(wk + o2);                         \
            ulonglong2 w3 = *(const ulonglong2*)(wk + o3);                         \
            FMA2(accA[0], xa, w0.x, accA[0]); FMA2(accA[1], xa, w0.y, accA[1]);    \
            FMA2(accA[2], xa, w1.x, accA[2]); FMA2(accA[3], xa, w1.y, accA[3]);    \
            FMA2(accA[4], xa, w2.x, accA[4]); FMA2(accA[5], xa, w2.y, accA[5]);    \
            FMA2(accA[6], xa, w3.x, accA[6]); FMA2(accA[7], xa, w3.y, accA[7]);    \
            FMA2(accB[0], xb, w0.x, accB[0]); FMA2(accB[1], xb, w0.y, accB[1]);    \
            FMA2(accB[2], xb, w1.x, accB[2]); FMA2(accB[3], xb, w1.y, accB[3]);    \
            FMA2(accB[4], xb, w2.x, accB[4]); FMA2(accB[5], xb, w2.y, accB[5]);    \
            FMA2(accB[6], xb, w3.x, accB[6]); FMA2(accB[7], xb, w3.y, accB[7]);    \
        }                                                                          \
    }

    float4 a0 = __ldg(xA + s), b0 = __ldg(xB + s);
    float4 a1, b1;
    #pragma unroll 1
    for (int c = 0; c < 32; c += 2) {
        a1 = __ldg(xA + 4 * (c + 1) + s);
        b1 = __ldg(xB + 4 * (c + 1) + s);
        G1_COMP(a0, b0, c);
        if (c + 2 < 32) {
            a0 = __ldg(xA + 4 * (c + 2) + s);
            b0 = __ldg(xB + 4 * (c + 2) + s);
        }
        G1_COMP(a1, b1, c + 1);
    }
#undef G1_COMP

    // combine the 4 k-slices within each 4-lane group (xor 1, 2 stay in-group)
    #pragma unroll
    for (int off = 1; off <= 2; off <<= 1) {
        #pragma unroll
        for (int q = 0; q < 8; q++) {
            ull oa = __shfl_xor_sync(0xffffffffu, accA[q], off);
            ull ob = __shfl_xor_sync(0xffffffffu, accB[q], off);
            ADD2(accA[q], accA[q], oa);
            ADD2(accB[q], accB[q], ob);
        }
    }

    if (s != 0) return;

    if (rowA < n) {
        const float di = s_dinv[rowA];
        ull dd;
        PACK2(dd, di);
        #pragma unroll
        for (int m = 0; m < 4; m++) {
            ull p0 = accA[2 * m], p1 = accA[2 * m + 1];
            MUL2(p0, p0, dd); MUL2(p1, p1, dd);
            s_g1[(size_t)rowA * 4 + m] =
                make_float4(lo32(p0), hi32(p0), lo32(p1), hi32(p1));
        }
    }
    if (rowB < n) {
        const float di = s_dinv[rowB];
        ull dd;
        PACK2(dd, di);
        #pragma unroll
        for (int m = 0; m < 4; m++) {
            ull p0 = accB[2 * m], p1 = accB[2 * m + 1];
            MUL2(p0, p0, dd); MUL2(p1, p1, dd);
            s_g1[(size_t)rowB * 4 + m] =
                make_float4(lo32(p0), hi32(p0), lo32(p1), hi32(p1));
        }
    }
}

// ================= layer-1 gather + fused mid =================
__global__ void __launch_bounds__(256) k_gather1(const float* __restrict__ b1,
                                                 const float* __restrict__ W2, int n) {
    __shared__ float W2s[HID * NCLS];
    __shared__ float b1s[HID];
    const int t = threadIdx.x;
    if (t < HID * NCLS) W2s[t] = W2[t];
    if (t < HID)        b1s[t] = b1[t];
    __syncthreads();

    const int g = (blockIdx.x * 256 + t) >> 2;
    const int m = t & 3;
    if (g >= n) return;

    const ulonglong2* G1 = (const ulonglong2*)s_g1;
    ulonglong2 acc = G1[(size_t)g * 4 + m];     // self-loop term
    const int cnt  = s_cnt[g];
    const int pcnt = (cnt + 7) & ~7;
    const int* cp  = s_csr + s_row[g];

    int ii[8];
    #pragma unroll
    for (int j = 0; j < 8; j++) ii[j] = __ldg(cp + j);

    for (int it = 0; it < pcnt; it += 8) {
        ulonglong2 v[8];
        #pragma unroll
        for (int j = 0; j < 8; j++) v[j] = __ldg(&G1[(size_t)ii[j] * 4 + m]);
        #pragma unroll
        for (int j = 0; j < 8; j++) ii[j] = __ldg(cp + it + 8 + j);  // prefetch
        #pragma unroll
        for (int j = 0; j < 8; j++) {
            ADD2(acc.x, acc.x, v[j].x);
            ADD2(acc.y, acc.y, v[j].y);
        }
    }

    const float di = s_dinv[g];
    float h[4];
    h[0] = fmaxf(fmaf(di, lo32(acc.x), b1s[m * 4 + 0]), 0.f);
    h[1] = fmaxf(fmaf(di, hi32(acc.x), b1s[m * 4 + 1]), 0.f);
    h[2] = fmaxf(fmaf(di, lo32(acc.y), b1s[m * 4 + 2]), 0.f);
    h[3] = fmaxf(fmaf(di, hi32(acc.y), b1s[m * 4 + 3]), 0.f);

    float u[8] = {0.f, 0.f, 0.f, 0.f, 0.f, 0.f, 0.f, 0.f};
    #pragma unroll
    for (int jj = 0; jj < 4; jj++) {
        const int j = m * 4 + jj;
        #pragma unroll
        for (int c = 0; c < NCLS; c++)
            u[c] = fmaf(h[jj], W2s[j * NCLS + c], u[c]);
    }

    ull p[4];
    PACKAB(p[0], u[0], u[1]);
    PACKAB(p[1], u[2], u[3]);
    PACKAB(p[2], u[4], u[5]);
    PACKAB(p[3], u[6], u[7]);
    #pragma unroll
    for (int off = 1; off <= 2; off <<= 1) {
        #pragma unroll
        for (int q = 0; q < 4; q++) {
            ull o = __shfl_xor_sync(0xffffffffu, p[q], off);
            ADD2(p[q], p[q], o);
        }
    }
    ull dd;
    PACK2(dd, di);
    #pragma unroll
    for (int q = 0; q < 4; q++) MUL2(p[q], p[q], dd);

    if (m == 0) {
        float4 v = make_float4(lo32(p[0]), hi32(p[0]), lo32(p[1]), hi32(p[1]));
        s_g2[(size_t)g * 2 + 0] = v;
    } else if (m == 1) {
        float4 v = make_float4(lo32(p[2]), hi32(p[2]), lo32(p[3]), hi32(p[3]));
        s_g2[(size_t)g * 2 + 1] = v;
    }
}

// ================= layer-2 gather + fused final output =================
__global__ void __launch_bounds__(256) k_gather2(const float* __restrict__ b2,
                                                 float* __restrict__ out, int n) {
    const int t = threadIdx.x;
    const int g = (blockIdx.x * 256 + t) >> 2;
    const int m = t & 3;
    if (g >= n) return;

    const ull* G2 = (const ull*)s_g2;
    ull acc = G2[(size_t)g * 4 + m];            // self-loop term
    const int cnt  = s_cnt[g];
    const int pcnt = (cnt + 7) & ~7;
    const int* cp  = s_csr + s_row[g];

    int ii[8];
    #pragma unroll
    for (int j = 0; j < 8; j++) ii[j] = __ldg(cp + j);

    for (int it = 0; it < pcnt; it += 8) {
        ull v[8];
        #pragma unroll
        for (int j = 0; j < 8; j++) v[j] = __ldg(&G2[(size_t)ii[j] * 4 + m]);
        #pragma unroll
        for (int j = 0; j < 8; j++) ii[j] = __ldg(cp + it + 8 + j);  // prefetch
        #pragma unroll
        for (int j = 0; j < 8; j++) ADD2(acc, acc, v[j]);
    }

    const float di = s_dinv[g];
    const int c0 = m * 2;
    float* orow = out + (size_t)g * NCLS;
    orow[c0] = fmaf(di, lo32(acc), __ldg(b2 + c0));
    if (c0 + 1 < NCLS)
        orow[c0 + 1] = fmaf(di, hi32(acc), __ldg(b2 + c0 + 1));
}

extern "C" void kernel_launch(void* const* d_in, const int* in_sizes, int n_in,
                              void* d_out, int out_size) {
    const float* x  = (const float*)d_in[0];
    const int*   ei = (const int*)  d_in[1];
    const float* W1 = (const float*)d_in[2];
    const float* b1 = (const float*)d_in[3];
    const float* W2 = (const float*)d_in[4];
    const float* b2 = (const float*)d_in[5];
    float* out = (float*)d_out;

    const int n = in_sizes[0] / IN_F;     // 100000
    const int e = in_sizes[1] / 2;        // 3200000
    const int* src = ei;
    const int* dst = ei + e;

    const int csr_len = e + 8 * n;
    const int csr4    = (csr_len + 3) / 4;

    const int nb = (n + 255) / 256;
    const int eb = (e + 255) / 256;
    const int zb = (csr4 > n ? csr4 + 255 : n + 255) / 256;
    const int gb = (n + G1_ROWS - 1) / G1_ROWS;   // 782 blocks
    const int g4 = (4 * n + 255) / 256;

    // gemm1 stays at launch index 3 (the ncu-profiled slot).
    k_zero   <<<zb, 256>>>(n, csr4);
    k_hist   <<<eb, 256>>>(dst, e);
    k_scanA  <<<nb, 256>>>(n);
    k_gemm1  <<<gb, 256>>>(x, W1, n);
    k_scanC  <<<nb, 256>>>(n);
    k_fill   <<<eb, 256>>>(src, dst, e);
    k_gather1<<<g4, 256>>>(b1, W2, n);
    k_gather2<<<g4, 256>>>(b2, out, n);
}